// round 8
// baseline (speedup 1.0000x reference)
#include <cuda_runtime.h>
#include <math.h>

#define DD 128
#define KK 256
#define NSLOT 8
#define BMAX 32768

// scratch: [query_raw | candidate_key | candidate_value], each B x 128 fp32
__device__ float g_scratch[3ull * BMAX * DD];

__device__ __forceinline__ float warp_sum(float v) {
#pragma unroll
    for (int o = 16; o; o >>= 1) v += __shfl_xor_sync(0xffffffffu, v, o);
    return v;
}
__device__ __forceinline__ float sigm(float x) { return 1.0f / (1.0f + expf(-x)); }
__device__ __forceinline__ float dot4(float4 a, float4 b) {
    return a.x * b.x + a.y * b.y + a.z * b.z + a.w * b.w;
}

__device__ __forceinline__ void fma2(unsigned long long& d, unsigned long long a,
                                     unsigned long long b) {
    asm("fma.rn.f32x2 %0, %1, %2, %0;" : "+l"(d) : "l"(a), "l"(b));
}

union V4U {
    float4 v;
    unsigned long long u[2];
};
union PU {
    unsigned long long u;
    float2 f;
};

// ---------------------------------------------------------------------------
// Kernel 1: fused GEMM with packed fp32x2 FMA. blockIdx.y = matrix id:
//   0: query_raw = [signal, previous] @ w_read_query          (no activation)
//   1: cand_key  = tanh([signal, hidden] @ w_key + b_key)
//   2: cand_val  = tanh([signal, hidden] @ w_value + b_value)
// Tile 128x128, K=256, 256 threads. Thread (tx,ty) owns rows
// {ty*4+i, 64+ty*4+i} and cols {tx*4+j, 64+tx*4+j}.
// A is stored DUPLICATED in smem so f32x2 "a" dup-pairs load for free.
// ---------------------------------------------------------------------------
__global__ __launch_bounds__(256, 2)
void fused_gemm(const float* __restrict__ signal,
                const float* __restrict__ previous,
                const float* __restrict__ hidden,
                const float* __restrict__ wrq,
                const float* __restrict__ wk, const float* __restrict__ bk,
                const float* __restrict__ wv, const float* __restrict__ bv,
                int B) {
    const int mid = blockIdx.y;
    const float* X2 = (mid == 0) ? previous : hidden;
    const float* W = (mid == 0) ? wrq : (mid == 1 ? wk : wv);
    const float* bias = (mid == 1) ? bk : bv;  // unused when mid == 0

    __shared__ __align__(16) float Xs2[16][2 * DD + 8];  // duplicated A
    __shared__ __align__(16) float Ws[16][DD];

    const int tid = threadIdx.x;
    const int tx = tid & 15;
    const int ty = tid >> 4;
    const int row0 = blockIdx.x * 128;

    unsigned long long acc2[8][4];
#pragma unroll
    for (int i = 0; i < 8; i++)
#pragma unroll
        for (int j = 0; j < 4; j++) acc2[i][j] = 0ull;

    for (int k0 = 0; k0 < KK; k0 += 16) {
        const float* Xsrc = (k0 < DD) ? signal : X2;
        const int kb = k0 & (DD - 1);
        // Load X tile (128 rows x 16 k), transposed + duplicated: Xs2[k][2m]=Xs2[k][2m+1]=X[m][k]
#pragma unroll
        for (int r = 0; r < 2; r++) {
            int slot = tid + r * 256;  // 0..511 float4 slots
            int m = slot >> 2;
            int f = slot & 3;
            float4 v = *reinterpret_cast<const float4*>(
                Xsrc + (size_t)(row0 + m) * DD + kb + f * 4);
            int m2 = 2 * m;
            *reinterpret_cast<float2*>(&Xs2[f * 4 + 0][m2]) = make_float2(v.x, v.x);
            *reinterpret_cast<float2*>(&Xs2[f * 4 + 1][m2]) = make_float2(v.y, v.y);
            *reinterpret_cast<float2*>(&Xs2[f * 4 + 2][m2]) = make_float2(v.z, v.z);
            *reinterpret_cast<float2*>(&Xs2[f * 4 + 3][m2]) = make_float2(v.w, v.w);
        }
        // Load W tile (16 k x 128 n), direct copy
#pragma unroll
        for (int r = 0; r < 2; r++) {
            int slot = tid + r * 256;
            int kk = slot >> 5;
            int nf = slot & 31;
            *reinterpret_cast<float4*>(&Ws[kk][nf * 4]) =
                *reinterpret_cast<const float4*>(W + (size_t)(k0 + kk) * DD + nf * 4);
        }
        __syncthreads();
#pragma unroll
        for (int kk = 0; kk < 16; kk++) {
            V4U ad0, ad1, ad2, ad3, bv0, bv1;
            ad0.v = *reinterpret_cast<float4*>(&Xs2[kk][ty * 8]);            // rows ty*4+0,1
            ad1.v = *reinterpret_cast<float4*>(&Xs2[kk][ty * 8 + 4]);        // rows ty*4+2,3
            ad2.v = *reinterpret_cast<float4*>(&Xs2[kk][2 * DD / 2 * 0 + 128 + ty * 8]);      // rows 64+ty*4+0,1
            ad3.v = *reinterpret_cast<float4*>(&Xs2[kk][128 + ty * 8 + 4]);  // rows 64+ty*4+2,3
            bv0.v = *reinterpret_cast<float4*>(&Ws[kk][tx * 4]);             // cols tx*4..+3
            bv1.v = *reinterpret_cast<float4*>(&Ws[kk][64 + tx * 4]);        // cols 64+tx*4..+3
            unsigned long long a2[8] = {ad0.u[0], ad0.u[1], ad1.u[0], ad1.u[1],
                                        ad2.u[0], ad2.u[1], ad3.u[0], ad3.u[1]};
            unsigned long long b2[4] = {bv0.u[0], bv0.u[1], bv1.u[0], bv1.u[1]};
#pragma unroll
            for (int i = 0; i < 8; i++)
#pragma unroll
                for (int j = 0; j < 4; j++) fma2(acc2[i][j], a2[i], b2[j]);
        }
        __syncthreads();
    }

    float* out = g_scratch + (size_t)mid * B * DD;
    float4 bb0 = make_float4(0, 0, 0, 0), bb1 = make_float4(0, 0, 0, 0);
    if (mid != 0) {
        bb0 = *reinterpret_cast<const float4*>(bias + tx * 4);
        bb1 = *reinterpret_cast<const float4*>(bias + 64 + tx * 4);
    }
#pragma unroll
    for (int i = 0; i < 8; i++) {
        int row = row0 + ((i < 4) ? (ty * 4 + i) : (64 + ty * 4 + i - 4));
#pragma unroll
        for (int half = 0; half < 2; half++) {
            PU p0, p1;
            p0.u = acc2[i][half * 2 + 0];
            p1.u = acc2[i][half * 2 + 1];
            float4 v = make_float4(p0.f.x, p0.f.y, p1.f.x, p1.f.y);
            if (mid != 0) {
                float4 bb = half ? bb1 : bb0;
                v.x = tanhf(v.x + bb.x);
                v.y = tanhf(v.y + bb.y);
                v.z = tanhf(v.z + bb.z);
                v.w = tanhf(v.w + bb.w);
            }
            *reinterpret_cast<float4*>(out + (size_t)row * DD + half * 64 + tx * 4) = v;
        }
    }
}

// ---------------------------------------------------------------------------
// Kernel 2: per-row epilogue. One warp per row, lane = 4 channels.
// Register-dieted: batched reduction partials, on-demand shuffles for
// strength/age, single fused value pass, streaming stores.
// ---------------------------------------------------------------------------
__global__ __launch_bounds__(256, 3)
void epilogue(const float* __restrict__ signal,
              const float* __restrict__ previous,
              const float* __restrict__ hidden,
              const float* __restrict__ keys,
              const float* __restrict__ values,
              const float* __restrict__ strength,
              const float* __restrict__ age,
              const float* __restrict__ wrm, const float* __restrict__ brm,
              const float* __restrict__ ww, const float* __restrict__ bw,
              const float* __restrict__ wp, const float* __restrict__ bp,
              const float* __restrict__ wm, const float* __restrict__ bm,
              float* __restrict__ out_mr,
              float* __restrict__ out_k,
              float* __restrict__ out_v,
              float* __restrict__ out_s,
              float* __restrict__ out_a,
              int B) {
    const int warp = threadIdx.x >> 5;
    const int lane = threadIdx.x & 31;
    const int row = blockIdx.x * 8 + warp;
    if (row >= B) return;
    const size_t rb = (size_t)row * DD;
    const int c = lane * 4;

    const float4 s4 = __ldcs(reinterpret_cast<const float4*>(signal + rb + c));
    const float4 p4 = __ldcs(reinterpret_cast<const float4*>(previous + rb + c));
    const float4 h4 = __ldcs(reinterpret_cast<const float4*>(hidden + rb + c));
    const float4 q4 = __ldcs(reinterpret_cast<const float4*>(g_scratch + rb + c));
    const float4 ck4 = __ldcs(reinterpret_cast<const float4*>(g_scratch + (size_t)B * DD + rb + c));

    // gate dot partials (reduced together for ILP)
    float g0, g1, g2, g3, qn, ckn;
    {
        const float4 wrm0 = *reinterpret_cast<const float4*>(wrm + c);
        const float4 wrm1 = *reinterpret_cast<const float4*>(wrm + DD + c);
        const float4 ww0 = *reinterpret_cast<const float4*>(ww + c);
        const float4 ww1 = *reinterpret_cast<const float4*>(ww + DD + c);
        const float4 wp0 = *reinterpret_cast<const float4*>(wp + c);
        const float4 wp1 = *reinterpret_cast<const float4*>(wp + DD + c);
        const float4 wm0 = *reinterpret_cast<const float4*>(wm + c);
        const float4 wm1 = *reinterpret_cast<const float4*>(wm + DD + c);
        g0 = warp_sum(dot4(s4, wrm0) + dot4(p4, wrm1));
        g1 = warp_sum(dot4(s4, ww0) + dot4(h4, ww1));
        g2 = warp_sum(dot4(s4, wp0) + dot4(h4, wp1));
        g3 = warp_sum(dot4(s4, wm0) + dot4(h4, wm1));
        qn = warp_sum(dot4(q4, q4));
        ckn = warp_sum(dot4(ck4, ck4));
    }
    const float rm = sigm(g0 + brm[0]);
    const float wsg = sigm(g1 + bw[0]);
    const float pers = sigm(g2 + bp[0]);
    const float mlog = g3 + bm[0];
    const float qinv = 1.0f / fmaxf(sqrtf(qn), 1e-6f);
    const float ckinv = 1.0f / fmaxf(sqrtf(ckn), 1e-6f);

    const size_t kb = (size_t)row * NSLOT * DD;

    // batched key-dot partials, then interleaved reductions
    float knp[8], qdp[8], cdp[8];
#pragma unroll
    for (int n = 0; n < 8; n++) {
        float4 k4 = *reinterpret_cast<const float4*>(keys + kb + n * DD + c);
        knp[n] = dot4(k4, k4);
        qdp[n] = dot4(q4, k4);
        cdp[n] = dot4(ck4, k4);
    }
    float cs[8], sim[8];
#pragma unroll
    for (int n = 0; n < 8; n++) {
        float kn = warp_sum(knp[n]);
        float qd = warp_sum(qdp[n]);
        float cd = warp_sum(cdp[n]);
        float kinv = 1.0f / fmaxf(sqrtf(kn), 1e-6f);
        cs[n] = qd * qinv * kinv;
        sim[n] = cd * ckinv * kinv;
    }

    // per-lane slot scalars (lane < 8 holds slot `lane`)
    const float myst = (lane < 8) ? strength[(size_t)row * 8 + lane] : 0.0f;
    const float myag = (lane < 8) ? age[(size_t)row * 8 + lane] : 0.0f;
    const float ps_self = (2.4f * myst + 0.6f * (1.0f - myag)) * 4.0f;
    const float rp_self = 1.2f * myag + (1.0f - myst);

    // content softmax (T=0.25 -> x4) and persistent softmax, combined weights
    float w[8];
    {
        float cmax = -1e30f, pmax = -1e30f;
        float ps[8];
#pragma unroll
        for (int n = 0; n < 8; n++) {
            cmax = fmaxf(cmax, cs[n]);
            ps[n] = __shfl_sync(0xffffffffu, ps_self, n);
            pmax = fmaxf(pmax, ps[n]);
        }
        float csum = 0.0f, psum = 0.0f;
        float cw[8];
#pragma unroll
        for (int n = 0; n < 8; n++) {
            cw[n] = expf((cs[n] - cmax) * 4.0f);
            csum += cw[n];
            ps[n] = expf(ps[n] - pmax);
            psum += ps[n];
        }
        float ci = rm / csum, pi = (1.0f - rm) / psum;
#pragma unroll
        for (int n = 0; n < 8; n++) w[n] = cw[n] * ci + ps[n] * pi;
    }

    // top-3 of similarity (first-occurrence tie-break, matching lax.top_k)
    float s0 = -1e30f; int i0 = 0;
#pragma unroll
    for (int n = 0; n < 8; n++) if (sim[n] > s0) { s0 = sim[n]; i0 = n; }
    float s1 = -1e30f; int i1 = 0;
#pragma unroll
    for (int n = 0; n < 8; n++) if (n != i0 && sim[n] > s1) { s1 = sim[n]; i1 = n; }
    float s2 = -1e30f; int i2 = 0;
#pragma unroll
    for (int n = 0; n < 8; n++) if (n != i0 && n != i1 && sim[n] > s2) { s2 = sim[n]; i2 = n; }

    const float nov = fminf(fmaxf(1.0f - s0, 0.0f), 1.0f);

    // replace argmax (first occurrence)
    float rbest = -1e30f; int ri = 0;
#pragma unroll
    for (int n = 0; n < 8; n++) {
        float rs = __shfl_sync(0xffffffffu, rp_self, n) + 0.5f * (1.0f - sim[n]);
        if (rs > rbest) { rbest = rs; ri = n; }
    }

    const float mpref = sigm(mlog + 2.6f * s0);
    const bool full_m = (s0 > 0.78f) && (mpref >= 0.55f);
    const bool multi_m = full_m && (s1 > 0.68f);
    const bool partial_m = (!multi_m) && (s0 > 0.64f) && (s1 > 0.52f);
    const bool merge_like = full_m || partial_m || multi_m;

    // partial softmax over {s0,s1}; multi softmax over {s0,s1,s2}
    const float pe = expf((s1 - s0) * 4.0f);
    const float pw0 = 1.0f / (1.0f + pe), pw1 = pe / (1.0f + pe);
    const float me1 = pe, me2 = expf((s2 - s0) * 4.0f);
    const float minv = 1.0f / (1.0f + me1 + me2);
    const float mw0 = minv, mw1 = me1 * minv, mw2 = me2 * minv;

    const float scale = multi_m ? (0.16f + 0.52f * wsg)
                                : (partial_m ? (0.18f + 0.62f * wsg) : (0.2f + 0.8f * wsg));
    const float osc = scale * (0.55f + 0.45f * nov);
    const float kmix = (merge_like ? (0.28f + 0.24f * pers) : (0.78f + 0.16f * pers)) * osc;
    const float vmix = (merge_like ? (0.42f + 0.28f * pers) : (0.82f + 0.12f * pers)) * osc;
    const float bf = 0.45f + 0.35f * pers + 0.45f * nov + 0.25f * wsg;

    float ow[8];
#pragma unroll
    for (int n = 0; n < 8; n++) {
        float tw = (n == ri) ? 1.0f : 0.0f;
        if (full_m) tw = (n == i0) ? 1.0f : 0.0f;
        if (partial_m) tw = (n == i0) ? pw0 : ((n == i1) ? pw1 : 0.0f);
        if (multi_m) tw = (n == i0) ? mw0 : ((n == i1) ? mw1 : ((n == i2) ? mw2 : 0.0f));
        ow[n] = tw;
    }

    const float4 cv4 = __ldcs(reinterpret_cast<const float4*>(g_scratch + 2ull * (size_t)B * DD + rb + c));

    // fused pass: weighted read + key/value update + strength/age
    float4 mr = make_float4(0, 0, 0, 0);
#pragma unroll
    for (int n = 0; n < 8; n++) {
        float4 k4 = *reinterpret_cast<const float4*>(keys + kb + n * DD + c);
        float4 v4 = *reinterpret_cast<const float4*>(values + kb + n * DD + c);
        float wn = w[n];
        mr.x = fmaf(wn, v4.x, mr.x);
        mr.y = fmaf(wn, v4.y, mr.y);
        mr.z = fmaf(wn, v4.z, mr.z);
        mr.w = fmaf(wn, v4.w, mr.w);

        float fk = ow[n] * kmix;
        float4 uk;
        uk.x = k4.x + fk * (ck4.x - k4.x);
        uk.y = k4.y + fk * (ck4.y - k4.y);
        uk.z = k4.z + fk * (ck4.z - k4.z);
        uk.w = k4.w + fk * (ck4.w - k4.w);
        __stcs(reinterpret_cast<float4*>(out_k + kb + n * DD + c), uk);

        float fv = ow[n] * vmix;
        float4 uv;
        uv.x = v4.x + fv * (cv4.x - v4.x);
        uv.y = v4.y + fv * (cv4.y - v4.y);
        uv.z = v4.z + fv * (cv4.z - v4.z);
        uv.w = v4.w + fv * (cv4.w - v4.w);
        __stcs(reinterpret_cast<float4*>(out_v + kb + n * DD + c), uv);

        if (lane == n) {
            float o = ow[n] * osc;
            out_s[(size_t)row * 8 + n] = fminf(fmaxf(myst * 0.99f + o * bf, 0.0f), 1.0f);
            out_a[(size_t)row * 8 + n] = fminf(fmaxf((myag + 0.02f) * (1.0f - o), 0.0f), 1.0f);
        }
    }
    __stcs(reinterpret_cast<float4*>(out_mr + rb + c), mr);
}

extern "C" void kernel_launch(void* const* d_in, const int* in_sizes, int n_in,
                              void* d_out, int out_size) {
    const float* signal   = (const float*)d_in[0];
    const float* previous = (const float*)d_in[1];
    const float* hidden   = (const float*)d_in[2];
    const float* keys     = (const float*)d_in[3];
    const float* values   = (const float*)d_in[4];
    const float* strength = (const float*)d_in[5];
    const float* age      = (const float*)d_in[6];
    const float* wrq      = (const float*)d_in[7];
    const float* wrm      = (const float*)d_in[8];
    const float* brm      = (const float*)d_in[9];
    const float* wk       = (const float*)d_in[10];
    const float* bk       = (const float*)d_in[11];
    const float* wv       = (const float*)d_in[12];
    const float* bv       = (const float*)d_in[13];
    const float* ww       = (const float*)d_in[14];
    const float* bw       = (const float*)d_in[15];
    const float* wp       = (const float*)d_in[16];
    const float* bp       = (const float*)d_in[17];
    const float* wm       = (const float*)d_in[18];
    const float* bm       = (const float*)d_in[19];

    const int B = in_sizes[0] / DD;

    float* out = (float*)d_out;
    float* out_mr = out;
    float* out_k = out_mr + (size_t)B * DD;
    float* out_v = out_k + (size_t)B * NSLOT * DD;
    float* out_s = out_v + (size_t)B * NSLOT * DD;
    float* out_a = out_s + (size_t)B * NSLOT;

    dim3 g1(B / 128, 3);
    fused_gemm<<<g1, 256>>>(signal, previous, hidden, wrq, wk, bk, wv, bv, B);

    epilogue<<<(B + 7) / 8, 256>>>(signal, previous, hidden, keys, values, strength, age,
                                   wrm, brm, ww, bw, wp, bp, wm, bm,
                                   out_mr, out_k, out_v, out_s, out_a, B);
}

// round 9
// speedup vs baseline: 1.0025x; 1.0025x over previous
#include <cuda_runtime.h>
#include <math.h>

#define DD 128
#define KK 256
#define NSLOT 8
#define BMAX 32768

// scratch: [query_raw | candidate_key | candidate_value], each B x 128 fp32
__device__ float g_scratch[3ull * BMAX * DD];

__device__ __forceinline__ float warp_sum(float v) {
#pragma unroll
    for (int o = 16; o; o >>= 1) v += __shfl_xor_sync(0xffffffffu, v, o);
    return v;
}
__device__ __forceinline__ float sigm(float x) { return 1.0f / (1.0f + expf(-x)); }
__device__ __forceinline__ float dot4(float4 a, float4 b) {
    return a.x * b.x + a.y * b.y + a.z * b.z + a.w * b.w;
}

__device__ __forceinline__ void fma2(unsigned long long& d, unsigned long long a,
                                     unsigned long long b) {
    asm("fma.rn.f32x2 %0, %1, %2, %0;" : "+l"(d) : "l"(a), "l"(b));
}

union V4U {
    float4 v;
    unsigned long long u[2];
};
union PU {
    unsigned long long u;
    float2 f;
};

// ---------------------------------------------------------------------------
// Kernel 1: fused GEMM with packed fp32x2 FMA. blockIdx.y = matrix id:
//   0: query_raw = [signal, previous] @ w_read_query          (no activation)
//   1: cand_key  = tanh([signal, hidden] @ w_key + b_key)
//   2: cand_val  = tanh([signal, hidden] @ w_value + b_value)
// Tile 128x128, K=256, 256 threads. Thread (tx,ty) owns rows
// {ty*4+i, 64+ty*4+i} and cols {tx*4+j, 64+tx*4+j}.
// A is stored DUPLICATED in smem so f32x2 "a" dup-pairs load for free.
// ---------------------------------------------------------------------------
__global__ __launch_bounds__(256, 2)
void fused_gemm(const float* __restrict__ signal,
                const float* __restrict__ previous,
                const float* __restrict__ hidden,
                const float* __restrict__ wrq,
                const float* __restrict__ wk, const float* __restrict__ bk,
                const float* __restrict__ wv, const float* __restrict__ bv,
                int B) {
    const int mid = blockIdx.y;
    const float* X2 = (mid == 0) ? previous : hidden;
    const float* W = (mid == 0) ? wrq : (mid == 1 ? wk : wv);
    const float* bias = (mid == 1) ? bk : bv;  // unused when mid == 0

    __shared__ __align__(16) float Xs2[16][2 * DD + 8];  // duplicated A
    __shared__ __align__(16) float Ws[16][DD];

    const int tid = threadIdx.x;
    const int tx = tid & 15;
    const int ty = tid >> 4;
    const int row0 = blockIdx.x * 128;

    unsigned long long acc2[8][4];
#pragma unroll
    for (int i = 0; i < 8; i++)
#pragma unroll
        for (int j = 0; j < 4; j++) acc2[i][j] = 0ull;

    for (int k0 = 0; k0 < KK; k0 += 16) {
        const float* Xsrc = (k0 < DD) ? signal : X2;
        const int kb = k0 & (DD - 1);
        // Load X tile (128 rows x 16 k), transposed + duplicated: Xs2[k][2m]=Xs2[k][2m+1]=X[m][k]
#pragma unroll
        for (int r = 0; r < 2; r++) {
            int slot = tid + r * 256;  // 0..511 float4 slots
            int m = slot >> 2;
            int f = slot & 3;
            float4 v = *reinterpret_cast<const float4*>(
                Xsrc + (size_t)(row0 + m) * DD + kb + f * 4);
            int m2 = 2 * m;
            *reinterpret_cast<float2*>(&Xs2[f * 4 + 0][m2]) = make_float2(v.x, v.x);
            *reinterpret_cast<float2*>(&Xs2[f * 4 + 1][m2]) = make_float2(v.y, v.y);
            *reinterpret_cast<float2*>(&Xs2[f * 4 + 2][m2]) = make_float2(v.z, v.z);
            *reinterpret_cast<float2*>(&Xs2[f * 4 + 3][m2]) = make_float2(v.w, v.w);
        }
        // Load W tile (16 k x 128 n), direct copy
#pragma unroll
        for (int r = 0; r < 2; r++) {
            int slot = tid + r * 256;
            int kk = slot >> 5;
            int nf = slot & 31;
            *reinterpret_cast<float4*>(&Ws[kk][nf * 4]) =
                *reinterpret_cast<const float4*>(W + (size_t)(k0 + kk) * DD + nf * 4);
        }
        __syncthreads();
#pragma unroll
        for (int kk = 0; kk < 16; kk++) {
            V4U ad0, ad1, ad2, ad3, bv0, bv1;
            ad0.v = *reinterpret_cast<float4*>(&Xs2[kk][ty * 8]);            // rows ty*4+0,1
            ad1.v = *reinterpret_cast<float4*>(&Xs2[kk][ty * 8 + 4]);        // rows ty*4+2,3
            ad2.v = *reinterpret_cast<float4*>(&Xs2[kk][2 * DD / 2 * 0 + 128 + ty * 8]);      // rows 64+ty*4+0,1
            ad3.v = *reinterpret_cast<float4*>(&Xs2[kk][128 + ty * 8 + 4]);  // rows 64+ty*4+2,3
            bv0.v = *reinterpret_cast<float4*>(&Ws[kk][tx * 4]);             // cols tx*4..+3
            bv1.v = *reinterpret_cast<float4*>(&Ws[kk][64 + tx * 4]);        // cols 64+tx*4..+3
            unsigned long long a2[8] = {ad0.u[0], ad0.u[1], ad1.u[0], ad1.u[1],
                                        ad2.u[0], ad2.u[1], ad3.u[0], ad3.u[1]};
            unsigned long long b2[4] = {bv0.u[0], bv0.u[1], bv1.u[0], bv1.u[1]};
#pragma unroll
            for (int i = 0; i < 8; i++)
#pragma unroll
                for (int j = 0; j < 4; j++) fma2(acc2[i][j], a2[i], b2[j]);
        }
        __syncthreads();
    }

    float* out = g_scratch + (size_t)mid * B * DD;
    float4 bb0 = make_float4(0, 0, 0, 0), bb1 = make_float4(0, 0, 0, 0);
    if (mid != 0) {
        bb0 = *reinterpret_cast<const float4*>(bias + tx * 4);
        bb1 = *reinterpret_cast<const float4*>(bias + 64 + tx * 4);
    }
#pragma unroll
    for (int i = 0; i < 8; i++) {
        int row = row0 + ((i < 4) ? (ty * 4 + i) : (64 + ty * 4 + i - 4));
#pragma unroll
        for (int half = 0; half < 2; half++) {
            PU p0, p1;
            p0.u = acc2[i][half * 2 + 0];
            p1.u = acc2[i][half * 2 + 1];
            float4 v = make_float4(p0.f.x, p0.f.y, p1.f.x, p1.f.y);
            if (mid != 0) {
                float4 bb = half ? bb1 : bb0;
                v.x = tanhf(v.x + bb.x);
                v.y = tanhf(v.y + bb.y);
                v.z = tanhf(v.z + bb.z);
                v.w = tanhf(v.w + bb.w);
            }
            *reinterpret_cast<float4*>(out + (size_t)row * DD + half * 64 + tx * 4) = v;
        }
    }
}

// ---------------------------------------------------------------------------
// Kernel 2: per-row epilogue. One warp per row, lane = 4 channels.
// Register-dieted: batched reduction partials, on-demand shuffles for
// strength/age, single fused value pass, streaming stores.
// ---------------------------------------------------------------------------
__global__ __launch_bounds__(256, 3)
void epilogue(const float* __restrict__ signal,
              const float* __restrict__ previous,
              const float* __restrict__ hidden,
              const float* __restrict__ keys,
              const float* __restrict__ values,
              const float* __restrict__ strength,
              const float* __restrict__ age,
              const float* __restrict__ wrm, const float* __restrict__ brm,
              const float* __restrict__ ww, const float* __restrict__ bw,
              const float* __restrict__ wp, const float* __restrict__ bp,
              const float* __restrict__ wm, const float* __restrict__ bm,
              float* __restrict__ out_mr,
              float* __restrict__ out_k,
              float* __restrict__ out_v,
              float* __restrict__ out_s,
              float* __restrict__ out_a,
              int B) {
    const int warp = threadIdx.x >> 5;
    const int lane = threadIdx.x & 31;
    const int row = blockIdx.x * 8 + warp;
    if (row >= B) return;
    const size_t rb = (size_t)row * DD;
    const int c = lane * 4;

    const float4 s4 = __ldcs(reinterpret_cast<const float4*>(signal + rb + c));
    const float4 p4 = __ldcs(reinterpret_cast<const float4*>(previous + rb + c));
    const float4 h4 = __ldcs(reinterpret_cast<const float4*>(hidden + rb + c));
    const float4 q4 = __ldcs(reinterpret_cast<const float4*>(g_scratch + rb + c));
    const float4 ck4 = __ldcs(reinterpret_cast<const float4*>(g_scratch + (size_t)B * DD + rb + c));

    // gate dot partials (reduced together for ILP)
    float g0, g1, g2, g3, qn, ckn;
    {
        const float4 wrm0 = *reinterpret_cast<const float4*>(wrm + c);
        const float4 wrm1 = *reinterpret_cast<const float4*>(wrm + DD + c);
        const float4 ww0 = *reinterpret_cast<const float4*>(ww + c);
        const float4 ww1 = *reinterpret_cast<const float4*>(ww + DD + c);
        const float4 wp0 = *reinterpret_cast<const float4*>(wp + c);
        const float4 wp1 = *reinterpret_cast<const float4*>(wp + DD + c);
        const float4 wm0 = *reinterpret_cast<const float4*>(wm + c);
        const float4 wm1 = *reinterpret_cast<const float4*>(wm + DD + c);
        g0 = warp_sum(dot4(s4, wrm0) + dot4(p4, wrm1));
        g1 = warp_sum(dot4(s4, ww0) + dot4(h4, ww1));
        g2 = warp_sum(dot4(s4, wp0) + dot4(h4, wp1));
        g3 = warp_sum(dot4(s4, wm0) + dot4(h4, wm1));
        qn = warp_sum(dot4(q4, q4));
        ckn = warp_sum(dot4(ck4, ck4));
    }
    const float rm = sigm(g0 + brm[0]);
    const float wsg = sigm(g1 + bw[0]);
    const float pers = sigm(g2 + bp[0]);
    const float mlog = g3 + bm[0];
    const float qinv = 1.0f / fmaxf(sqrtf(qn), 1e-6f);
    const float ckinv = 1.0f / fmaxf(sqrtf(ckn), 1e-6f);

    const size_t kb = (size_t)row * NSLOT * DD;

    // batched key-dot partials, then interleaved reductions
    float knp[8], qdp[8], cdp[8];
#pragma unroll
    for (int n = 0; n < 8; n++) {
        float4 k4 = *reinterpret_cast<const float4*>(keys + kb + n * DD + c);
        knp[n] = dot4(k4, k4);
        qdp[n] = dot4(q4, k4);
        cdp[n] = dot4(ck4, k4);
    }
    float cs[8], sim[8];
#pragma unroll
    for (int n = 0; n < 8; n++) {
        float kn = warp_sum(knp[n]);
        float qd = warp_sum(qdp[n]);
        float cd = warp_sum(cdp[n]);
        float kinv = 1.0f / fmaxf(sqrtf(kn), 1e-6f);
        cs[n] = qd * qinv * kinv;
        sim[n] = cd * ckinv * kinv;
    }

    // per-lane slot scalars (lane < 8 holds slot `lane`)
    const float myst = (lane < 8) ? strength[(size_t)row * 8 + lane] : 0.0f;
    const float myag = (lane < 8) ? age[(size_t)row * 8 + lane] : 0.0f;
    const float ps_self = (2.4f * myst + 0.6f * (1.0f - myag)) * 4.0f;
    const float rp_self = 1.2f * myag + (1.0f - myst);

    // content softmax (T=0.25 -> x4) and persistent softmax, combined weights
    float w[8];
    {
        float cmax = -1e30f, pmax = -1e30f;
        float ps[8];
#pragma unroll
        for (int n = 0; n < 8; n++) {
            cmax = fmaxf(cmax, cs[n]);
            ps[n] = __shfl_sync(0xffffffffu, ps_self, n);
            pmax = fmaxf(pmax, ps[n]);
        }
        float csum = 0.0f, psum = 0.0f;
        float cw[8];
#pragma unroll
        for (int n = 0; n < 8; n++) {
            cw[n] = expf((cs[n] - cmax) * 4.0f);
            csum += cw[n];
            ps[n] = expf(ps[n] - pmax);
            psum += ps[n];
        }
        float ci = rm / csum, pi = (1.0f - rm) / psum;
#pragma unroll
        for (int n = 0; n < 8; n++) w[n] = cw[n] * ci + ps[n] * pi;
    }

    // top-3 of similarity (first-occurrence tie-break, matching lax.top_k)
    float s0 = -1e30f; int i0 = 0;
#pragma unroll
    for (int n = 0; n < 8; n++) if (sim[n] > s0) { s0 = sim[n]; i0 = n; }
    float s1 = -1e30f; int i1 = 0;
#pragma unroll
    for (int n = 0; n < 8; n++) if (n != i0 && sim[n] > s1) { s1 = sim[n]; i1 = n; }
    float s2 = -1e30f; int i2 = 0;
#pragma unroll
    for (int n = 0; n < 8; n++) if (n != i0 && n != i1 && sim[n] > s2) { s2 = sim[n]; i2 = n; }

    const float nov = fminf(fmaxf(1.0f - s0, 0.0f), 1.0f);

    // replace argmax (first occurrence)
    float rbest = -1e30f; int ri = 0;
#pragma unroll
    for (int n = 0; n < 8; n++) {
        float rs = __shfl_sync(0xffffffffu, rp_self, n) + 0.5f * (1.0f - sim[n]);
        if (rs > rbest) { rbest = rs; ri = n; }
    }

    const float mpref = sigm(mlog + 2.6f * s0);
    const bool full_m = (s0 > 0.78f) && (mpref >= 0.55f);
    const bool multi_m = full_m && (s1 > 0.68f);
    const bool partial_m = (!multi_m) && (s0 > 0.64f) && (s1 > 0.52f);
    const bool merge_like = full_m || partial_m || multi_m;

    // partial softmax over {s0,s1}; multi softmax over {s0,s1,s2}
    const float pe = expf((s1 - s0) * 4.0f);
    const float pw0 = 1.0f / (1.0f + pe), pw1 = pe / (1.0f + pe);
    const float me1 = pe, me2 = expf((s2 - s0) * 4.0f);
    const float minv = 1.0f / (1.0f + me1 + me2);
    const float mw0 = minv, mw1 = me1 * minv, mw2 = me2 * minv;

    const float scale = multi_m ? (0.16f + 0.52f * wsg)
                                : (partial_m ? (0.18f + 0.62f * wsg) : (0.2f + 0.8f * wsg));
    const float osc = scale * (0.55f + 0.45f * nov);
    const float kmix = (merge_like ? (0.28f + 0.24f * pers) : (0.78f + 0.16f * pers)) * osc;
    const float vmix = (merge_like ? (0.42f + 0.28f * pers) : (0.82f + 0.12f * pers)) * osc;
    const float bf = 0.45f + 0.35f * pers + 0.45f * nov + 0.25f * wsg;

    float ow[8];
#pragma unroll
    for (int n = 0; n < 8; n++) {
        float tw = (n == ri) ? 1.0f : 0.0f;
        if (full_m) tw = (n == i0) ? 1.0f : 0.0f;
        if (partial_m) tw = (n == i0) ? pw0 : ((n == i1) ? pw1 : 0.0f);
        if (multi_m) tw = (n == i0) ? mw0 : ((n == i1) ? mw1 : ((n == i2) ? mw2 : 0.0f));
        ow[n] = tw;
    }

    const float4 cv4 = __ldcs(reinterpret_cast<const float4*>(g_scratch + 2ull * (size_t)B * DD + rb + c));

    // fused pass: weighted read + key/value update + strength/age
    float4 mr = make_float4(0, 0, 0, 0);
#pragma unroll
    for (int n = 0; n < 8; n++) {
        float4 k4 = *reinterpret_cast<const float4*>(keys + kb + n * DD + c);
        float4 v4 = *reinterpret_cast<const float4*>(values + kb + n * DD + c);
        float wn = w[n];
        mr.x = fmaf(wn, v4.x, mr.x);
        mr.y = fmaf(wn, v4.y, mr.y);
        mr.z = fmaf(wn, v4.z, mr.z);
        mr.w = fmaf(wn, v4.w, mr.w);

        float fk = ow[n] * kmix;
        float4 uk;
        uk.x = k4.x + fk * (ck4.x - k4.x);
        uk.y = k4.y + fk * (ck4.y - k4.y);
        uk.z = k4.z + fk * (ck4.z - k4.z);
        uk.w = k4.w + fk * (ck4.w - k4.w);
        __stcs(reinterpret_cast<float4*>(out_k + kb + n * DD + c), uk);

        float fv = ow[n] * vmix;
        float4 uv;
        uv.x = v4.x + fv * (cv4.x - v4.x);
        uv.y = v4.y + fv * (cv4.y - v4.y);
        uv.z = v4.z + fv * (cv4.z - v4.z);
        uv.w = v4.w + fv * (cv4.w - v4.w);
        __stcs(reinterpret_cast<float4*>(out_v + kb + n * DD + c), uv);

        if (lane == n) {
            float o = ow[n] * osc;
            out_s[(size_t)row * 8 + n] = fminf(fmaxf(myst * 0.99f + o * bf, 0.0f), 1.0f);
            out_a[(size_t)row * 8 + n] = fminf(fmaxf((myag + 0.02f) * (1.0f - o), 0.0f), 1.0f);
        }
    }
    __stcs(reinterpret_cast<float4*>(out_mr + rb + c), mr);
}

extern "C" void kernel_launch(void* const* d_in, const int* in_sizes, int n_in,
                              void* d_out, int out_size) {
    const float* signal   = (const float*)d_in[0];
    const float* previous = (const float*)d_in[1];
    const float* hidden   = (const float*)d_in[2];
    const float* keys     = (const float*)d_in[3];
    const float* values   = (const float*)d_in[4];
    const float* strength = (const float*)d_in[5];
    const float* age      = (const float*)d_in[6];
    const float* wrq      = (const float*)d_in[7];
    const float* wrm      = (const float*)d_in[8];
    const float* brm      = (const float*)d_in[9];
    const float* wk       = (const float*)d_in[10];
    const float* bk       = (const float*)d_in[11];
    const float* wv       = (const float*)d_in[12];
    const float* bv       = (const float*)d_in[13];
    const float* ww       = (const float*)d_in[14];
    const float* bw       = (const float*)d_in[15];
    const float* wp       = (const float*)d_in[16];
    const float* bp       = (const float*)d_in[17];
    const float* wm       = (const float*)d_in[18];
    const float* bm       = (const float*)d_in[19];

    const int B = in_sizes[0] / DD;

    float* out = (float*)d_out;
    float* out_mr = out;
    float* out_k = out_mr + (size_t)B * DD;
    float* out_v = out_k + (size_t)B * NSLOT * DD;
    float* out_s = out_v + (size_t)B * NSLOT * DD;
    float* out_a = out_s + (size_t)B * NSLOT;

    dim3 g1(B / 128, 3);
    fused_gemm<<<g1, 256>>>(signal, previous, hidden, wrq, wk, bk, wv, bv, B);

    epilogue<<<(B + 7) / 8, 256>>>(signal, previous, hidden, keys, values, strength, age,
                                   wrm, brm, ww, bw, wp, bp, wm, bm,
                                   out_mr, out_k, out_v, out_s, out_a, B);
}

// round 11
// speedup vs baseline: 1.5678x; 1.5640x over previous
#include <cuda_runtime.h>
#include <cuda_bf16.h>
#include <math.h>

#define DD 128
#define KK 256
#define NSLOT 8
#define BMAX 32768

// scratch: [query_raw | candidate_key | candidate_value], each B x 128 fp32
__device__ float g_scratch[3ull * BMAX * DD];
// pre-transposed weights, bf16 hi/lo split: [mid][hi/lo][n*256+k]
__device__ __nv_bfloat16 g_wt[3][2][DD * KK];

// ---------------- helpers ----------------
__device__ __forceinline__ unsigned smem_u32(const void* p) {
    unsigned a;
    asm("{ .reg .u64 t; cvta.to.shared.u64 t, %1; cvt.u32.u64 %0, t; }" : "=r"(a) : "l"(p));
    return a;
}
__device__ __forceinline__ void ldmat4(unsigned* r, unsigned addr) {
    asm volatile("ldmatrix.sync.aligned.m8n8.x4.shared.b16 {%0,%1,%2,%3}, [%4];"
                 : "=r"(r[0]), "=r"(r[1]), "=r"(r[2]), "=r"(r[3])
                 : "r"(addr));
}
__device__ __forceinline__ void mma_bf16(float* d, const unsigned* a, unsigned b0, unsigned b1) {
    asm volatile(
        "mma.sync.aligned.m16n8k16.row.col.f32.bf16.bf16.f32 "
        "{%0,%1,%2,%3}, {%4,%5,%6,%7}, {%8,%9}, {%0,%1,%2,%3};"
        : "+f"(d[0]), "+f"(d[1]), "+f"(d[2]), "+f"(d[3])
        : "r"(a[0]), "r"(a[1]), "r"(a[2]), "r"(a[3]), "r"(b0), "r"(b1));
}
__device__ __forceinline__ unsigned bf2u(__nv_bfloat162 v) {
    return *reinterpret_cast<unsigned*>(&v);
}
__device__ __forceinline__ float fast_tanh(float x) {
    float e = __expf(2.0f * x);
    return 1.0f - 2.0f / (e + 1.0f);
}
__device__ __forceinline__ float warp_sum(float v) {
#pragma unroll
    for (int o = 16; o; o >>= 1) v += __shfl_xor_sync(0xffffffffu, v, o);
    return v;
}
__device__ __forceinline__ float sigm(float x) { return 1.0f / (1.0f + expf(-x)); }
__device__ __forceinline__ float dot4(float4 a, float4 b) {
    return a.x * b.x + a.y * b.y + a.z * b.z + a.w * b.w;
}

// ---------------------------------------------------------------------------
// Kernel 0: transpose + bf16-split weights. W[k][n] -> Wt_hi/lo[n][k].
// ---------------------------------------------------------------------------
__global__ __launch_bounds__(256)
void prep_wt(const float* __restrict__ wrq, const float* __restrict__ wk,
             const float* __restrict__ wv) {
    const int mid = blockIdx.y;
    const float* W = (mid == 0) ? wrq : (mid == 1 ? wk : wv);
    int tid = blockIdx.x * 256 + threadIdx.x;  // 0..32767
    int k = tid >> 7;
    int n = tid & 127;
    float x = W[k * DD + n];
    __nv_bfloat16 hi = __float2bfloat16(x);
    float lo = x - __bfloat162float(hi);
    g_wt[mid][0][n * KK + k] = hi;
    g_wt[mid][1][n * KK + k] = __float2bfloat16(lo);
}

// ---------------------------------------------------------------------------
// Kernel 1: bf16-split GEMM via mma.sync (HMMA tensor path, compute_103-safe).
//   blockIdx.z = matrix id, blockIdx.y = N-half (64 cols), blockIdx.x = M/128.
//   K=256 in 4 quarters of 64. fp32 accum; products Ah*Bh + Ah*Bl + Al*Bh.
// Smem: A hi/lo [128][72] bf16 (144B pitch), B hi/lo [64][72] bf16.
// 144B pitch -> ldmatrix phases hit (r+c) mod 8 distinct 16B chunks: no conflicts.
// ---------------------------------------------------------------------------
#define APITCH_B 144
__global__ __launch_bounds__(256, 2)
void gemm_mma(const float* __restrict__ signal,
              const float* __restrict__ previous,
              const float* __restrict__ hidden,
              const float* __restrict__ bk, const float* __restrict__ bv,
              int B) {
    extern __shared__ __align__(16) char smem[];
    const unsigned A_H = 0;
    const unsigned A_L = 128 * APITCH_B;           // 18432
    const unsigned B_H = 2u * 128 * APITCH_B;      // 36864
    const unsigned B_L = B_H + 64 * APITCH_B;      // 46080; total 55296
    const unsigned sb = smem_u32(smem);

    const int tid = threadIdx.x;
    const int wid = tid >> 5;
    const int lane = tid & 31;
    const int mid = blockIdx.z;
    const int col0 = blockIdx.y * 64;
    const int row0 = blockIdx.x * 128;
    const float* X2 = (mid == 0) ? previous : hidden;
    const __nv_bfloat16* wth = &g_wt[mid][0][0];
    const __nv_bfloat16* wtl = &g_wt[mid][1][0];

    float acc[4][2][4];
#pragma unroll
    for (int i = 0; i < 4; i++)
#pragma unroll
        for (int j = 0; j < 2; j++)
#pragma unroll
            for (int e = 0; e < 4; e++) acc[i][j][e] = 0.0f;

    // warp tile: rows wm..wm+63 (4 m-atoms), cols wn..wn+15 (2 n-atoms)
    const int wm = (wid & 1) * 64;
    const int wn = (wid >> 1) * 16;
    // ldmatrix lane offsets
    const unsigned aOff = (unsigned)(wm + (lane & 15)) * APITCH_B + (lane >> 4) * 16;
    const unsigned bOff = (unsigned)(wn + ((lane >> 4) & 1) * 8 + (lane & 7)) * APITCH_B +
                          ((lane >> 3) & 1) * 16;

    for (int q = 0; q < 4; q++) {
        const int kbase = q * 64;
        const float* Xsrc = (kbase < DD) ? signal : X2;
        const int kloc = kbase & (DD - 1);
        // fill A hi/lo: 128 rows x 64 k fp32 -> bf16 split
#pragma unroll
        for (int i = 0; i < 8; i++) {
            int f = tid + i * 256;
            int r = f >> 4, c4 = f & 15;
            float4 x = *reinterpret_cast<const float4*>(
                Xsrc + (size_t)(row0 + r) * DD + kloc + c4 * 4);
            __nv_bfloat162 h0 = __float22bfloat162_rn(make_float2(x.x, x.y));
            __nv_bfloat162 h1 = __float22bfloat162_rn(make_float2(x.z, x.w));
            float2 hf0 = __bfloat1622float2(h0);
            float2 hf1 = __bfloat1622float2(h1);
            __nv_bfloat162 l0 = __float22bfloat162_rn(make_float2(x.x - hf0.x, x.y - hf0.y));
            __nv_bfloat162 l1 = __float22bfloat162_rn(make_float2(x.z - hf1.x, x.w - hf1.y));
            unsigned off = (unsigned)r * APITCH_B + c4 * 8;
            *reinterpret_cast<uint2*>(smem + A_H + off) = make_uint2(bf2u(h0), bf2u(h1));
            *reinterpret_cast<uint2*>(smem + A_L + off) = make_uint2(bf2u(l0), bf2u(l1));
        }
        // fill B hi/lo: 64 n x 64 k bf16 (already split in gmem)
#pragma unroll
        for (int i = 0; i < 4; i++) {
            int u = tid + i * 256;
            int n = u >> 4, kc = u & 15;
            size_t src = (size_t)(col0 + n) * KK + kbase + kc * 4;
            uint2 hv = *reinterpret_cast<const uint2*>(wth + src);
            uint2 lv = *reinterpret_cast<const uint2*>(wtl + src);
            unsigned off = (unsigned)n * APITCH_B + kc * 8;
            *reinterpret_cast<uint2*>(smem + B_H + off) = hv;
            *reinterpret_cast<uint2*>(smem + B_L + off) = lv;
        }
        __syncthreads();

#pragma unroll
        for (int ks = 0; ks < 4; ks++) {
            unsigned bh[4], bl[4];
            ldmat4(bh, sb + B_H + bOff + ks * 32);
            ldmat4(bl, sb + B_L + bOff + ks * 32);
#pragma unroll
            for (int am = 0; am < 4; am++) {
                unsigned ah[4], al[4];
                unsigned aoff = aOff + (unsigned)am * (16 * APITCH_B) + ks * 32;
                ldmat4(ah, sb + A_H + aoff);
                ldmat4(al, sb + A_L + aoff);
                mma_bf16(acc[am][0], ah, bh[0], bh[1]);
                mma_bf16(acc[am][0], ah, bl[0], bl[1]);
                mma_bf16(acc[am][0], al, bh[0], bh[1]);
                mma_bf16(acc[am][1], ah, bh[2], bh[3]);
                mma_bf16(acc[am][1], ah, bl[2], bl[3]);
                mma_bf16(acc[am][1], al, bh[2], bh[3]);
            }
        }
        __syncthreads();
    }

    // writeback: d0,d1 -> row (lane>>2), cols (lane&3)*2..+1; d2,d3 -> row+8
    float* out = g_scratch + (size_t)mid * B * DD;
    const float* bias = (mid == 1) ? bk : bv;
    const int qrow = lane >> 2;
    const int qcol = (lane & 3) * 2;
#pragma unroll
    for (int am = 0; am < 4; am++) {
        int r0 = row0 + wm + am * 16 + qrow;
#pragma unroll
        for (int bn = 0; bn < 2; bn++) {
            int cc = col0 + wn + bn * 8 + qcol;
            float2 v0 = make_float2(acc[am][bn][0], acc[am][bn][1]);
            float2 v1 = make_float2(acc[am][bn][2], acc[am][bn][3]);
            if (mid != 0) {
                float2 bb = *reinterpret_cast<const float2*>(bias + cc);
                v0.x = fast_tanh(v0.x + bb.x);
                v0.y = fast_tanh(v0.y + bb.y);
                v1.x = fast_tanh(v1.x + bb.x);
                v1.y = fast_tanh(v1.y + bb.y);
            }
            *reinterpret_cast<float2*>(out + (size_t)r0 * DD + cc) = v0;
            *reinterpret_cast<float2*>(out + (size_t)(r0 + 8) * DD + cc) = v1;
        }
    }
}

// ---------------------------------------------------------------------------
// Kernel 2: per-row epilogue (unchanged; at LTS-cap roofline).
// ---------------------------------------------------------------------------
__global__ __launch_bounds__(256, 3)
void epilogue(const float* __restrict__ signal,
              const float* __restrict__ previous,
              const float* __restrict__ hidden,
              const float* __restrict__ keys,
              const float* __restrict__ values,
              const float* __restrict__ strength,
              const float* __restrict__ age,
              const float* __restrict__ wrm, const float* __restrict__ brm,
              const float* __restrict__ ww, const float* __restrict__ bw,
              const float* __restrict__ wp, const float* __restrict__ bp,
              const float* __restrict__ wm, const float* __restrict__ bm,
              float* __restrict__ out_mr,
              float* __restrict__ out_k,
              float* __restrict__ out_v,
              float* __restrict__ out_s,
              float* __restrict__ out_a,
              int B) {
    const int warp = threadIdx.x >> 5;
    const int lane = threadIdx.x & 31;
    const int row = blockIdx.x * 8 + warp;
    if (row >= B) return;
    const size_t rb = (size_t)row * DD;
    const int c = lane * 4;

    const float4 s4 = __ldcs(reinterpret_cast<const float4*>(signal + rb + c));
    const float4 p4 = __ldcs(reinterpret_cast<const float4*>(previous + rb + c));
    const float4 h4 = __ldcs(reinterpret_cast<const float4*>(hidden + rb + c));
    const float4 q4 = __ldcs(reinterpret_cast<const float4*>(g_scratch + rb + c));
    const float4 ck4 = __ldcs(reinterpret_cast<const float4*>(g_scratch + (size_t)B * DD + rb + c));

    float g0, g1, g2, g3, qn, ckn;
    {
        const float4 wrm0 = *reinterpret_cast<const float4*>(wrm + c);
        const float4 wrm1 = *reinterpret_cast<const float4*>(wrm + DD + c);
        const float4 ww0 = *reinterpret_cast<const float4*>(ww + c);
        const float4 ww1 = *reinterpret_cast<const float4*>(ww + DD + c);
        const float4 wp0 = *reinterpret_cast<const float4*>(wp + c);
        const float4 wp1 = *reinterpret_cast<const float4*>(wp + DD + c);
        const float4 wm0 = *reinterpret_cast<const float4*>(wm + c);
        const float4 wm1 = *reinterpret_cast<const float4*>(wm + DD + c);
        g0 = warp_sum(dot4(s4, wrm0) + dot4(p4, wrm1));
        g1 = warp_sum(dot4(s4, ww0) + dot4(h4, ww1));
        g2 = warp_sum(dot4(s4, wp0) + dot4(h4, wp1));
        g3 = warp_sum(dot4(s4, wm0) + dot4(h4, wm1));
        qn = warp_sum(dot4(q4, q4));
        ckn = warp_sum(dot4(ck4, ck4));
    }
    const float rm = sigm(g0 + brm[0]);
    const float wsg = sigm(g1 + bw[0]);
    const float pers = sigm(g2 + bp[0]);
    const float mlog = g3 + bm[0];
    const float qinv = 1.0f / fmaxf(sqrtf(qn), 1e-6f);
    const float ckinv = 1.0f / fmaxf(sqrtf(ckn), 1e-6f);

    const size_t kb = (size_t)row * NSLOT * DD;

    float knp[8], qdp[8], cdp[8];
#pragma unroll
    for (int n = 0; n < 8; n++) {
        float4 k4 = *reinterpret_cast<const float4*>(keys + kb + n * DD + c);
        knp[n] = dot4(k4, k4);
        qdp[n] = dot4(q4, k4);
        cdp[n] = dot4(ck4, k4);
    }
    float cs[8], sim[8];
#pragma unroll
    for (int n = 0; n < 8; n++) {
        float kn = warp_sum(knp[n]);
        float qd = warp_sum(qdp[n]);
        float cd = warp_sum(cdp[n]);
        float kinv = 1.0f / fmaxf(sqrtf(kn), 1e-6f);
        cs[n] = qd * qinv * kinv;
        sim[n] = cd * ckinv * kinv;
    }

    const float myst = (lane < 8) ? strength[(size_t)row * 8 + lane] : 0.0f;
    const float myag = (lane < 8) ? age[(size_t)row * 8 + lane] : 0.0f;
    const float ps_self = (2.4f * myst + 0.6f * (1.0f - myag)) * 4.0f;
    const float rp_self = 1.2f * myag + (1.0f - myst);

    float w[8];
    {
        float cmax = -1e30f, pmax = -1e30f;
        float ps[8];
#pragma unroll
        for (int n = 0; n < 8; n++) {
            cmax = fmaxf(cmax, cs[n]);
            ps[n] = __shfl_sync(0xffffffffu, ps_self, n);
            pmax = fmaxf(pmax, ps[n]);
        }
        float csum = 0.0f, psum = 0.0f;
        float cw[8];
#pragma unroll
        for (int n = 0; n < 8; n++) {
            cw[n] = expf((cs[n] - cmax) * 4.0f);
            csum += cw[n];
            ps[n] = expf(ps[n] - pmax);
            psum += ps[n];
        }
        float ci = rm / csum, pi = (1.0f - rm) / psum;
#pragma unroll
        for (int n = 0; n < 8; n++) w[n] = cw[n] * ci + ps[n] * pi;
    }

    float s0 = -1e30f; int i0 = 0;
#pragma unroll
    for (int n = 0; n < 8; n++) if (sim[n] > s0) { s0 = sim[n]; i0 = n; }
    float s1 = -1e30f; int i1 = 0;
#pragma unroll
    for (int n = 0; n < 8; n++) if (n != i0 && sim[n] > s1) { s1 = sim[n]; i1 = n; }
    float s2 = -1e30f; int i2 = 0;
#pragma unroll
    for (int n = 0; n < 8; n++) if (n != i0 && n != i1 && sim[n] > s2) { s2 = sim[n]; i2 = n; }

    const float nov = fminf(fmaxf(1.0f - s0, 0.0f), 1.0f);

    float rbest = -1e30f; int ri = 0;
#pragma unroll
    for (int n = 0; n < 8; n++) {
        float rs = __shfl_sync(0xffffffffu, rp_self, n) + 0.5f * (1.0f - sim[n]);
        if (rs > rbest) { rbest = rs; ri = n; }
    }

    const float mpref = sigm(mlog + 2.6f * s0);
    const bool full_m = (s0 > 0.78f) && (mpref >= 0.55f);
    const bool multi_m = full_m && (s1 > 0.68f);
    const bool partial_m = (!multi_m) && (s0 > 0.64f) && (s1 > 0.52f);
    const bool merge_like = full_m || partial_m || multi_m;

    const float pe = expf((s1 - s0) * 4.0f);
    const float pw0 = 1.0f / (1.0f + pe), pw1 = pe / (1.0f + pe);
    const float me1 = pe, me2 = expf((s2 - s0) * 4.0f);
    const float minv = 1.0f / (1.0f + me1 + me2);
    const float mw0 = minv, mw1 = me1 * minv, mw2 = me2 * minv;

    const float scale = multi_m ? (0.16f + 0.52f * wsg)
                                : (partial_m ? (0.18f + 0.62f * wsg) : (0.2f + 0.8f * wsg));
    const float osc = scale * (0.55f + 0.45f * nov);
    const float kmix = (merge_like ? (0.28f + 0.24f * pers) : (0.78f + 0.16f * pers)) * osc;
    const float vmix = (merge_like ? (0.42f + 0.28f * pers) : (0.82f + 0.12f * pers)) * osc;
    const float bf = 0.45f + 0.35f * pers + 0.45f * nov + 0.25f * wsg;

    float ow[8];
#pragma unroll
    for (int n = 0; n < 8; n++) {
        float tw = (n == ri) ? 1.0f : 0.0f;
        if (full_m) tw = (n == i0) ? 1.0f : 0.0f;
        if (partial_m) tw = (n == i0) ? pw0 : ((n == i1) ? pw1 : 0.0f);
        if (multi_m) tw = (n == i0) ? mw0 : ((n == i1) ? mw1 : ((n == i2) ? mw2 : 0.0f));
        ow[n] = tw;
    }

    const float4 cv4 = __ldcs(reinterpret_cast<const float4*>(g_scratch + 2ull * (size_t)B * DD + rb + c));

    float4 mr = make_float4(0, 0, 0, 0);
#pragma unroll
    for (int n = 0; n < 8; n++) {
        float4 k4 = *reinterpret_cast<const float4*>(keys + kb + n * DD + c);
        float4 v4 = *reinterpret_cast<const float4*>(values + kb + n * DD + c);
        float wn = w[n];
        mr.x = fmaf(wn, v4.x, mr.x);
        mr.y = fmaf(wn, v4.y, mr.y);
        mr.z = fmaf(wn, v4.z, mr.z);
        mr.w = fmaf(wn, v4.w, mr.w);

        float fk = ow[n] * kmix;
        float4 uk;
        uk.x = k4.x + fk * (ck4.x - k4.x);
        uk.y = k4.y + fk * (ck4.y - k4.y);
        uk.z = k4.z + fk * (ck4.z - k4.z);
        uk.w = k4.w + fk * (ck4.w - k4.w);
        __stcs(reinterpret_cast<float4*>(out_k + kb + n * DD + c), uk);

        float fv = ow[n] * vmix;
        float4 uv;
        uv.x = v4.x + fv * (cv4.x - v4.x);
        uv.y = v4.y + fv * (cv4.y - v4.y);
        uv.z = v4.z + fv * (cv4.z - v4.z);
        uv.w = v4.w + fv * (cv4.w - v4.w);
        __stcs(reinterpret_cast<float4*>(out_v + kb + n * DD + c), uv);

        if (lane == n) {
            float o = ow[n] * osc;
            out_s[(size_t)row * 8 + n] = fminf(fmaxf(myst * 0.99f + o * bf, 0.0f), 1.0f);
            out_a[(size_t)row * 8 + n] = fminf(fmaxf((myag + 0.02f) * (1.0f - o), 0.0f), 1.0f);
        }
    }
    __stcs(reinterpret_cast<float4*>(out_mr + rb + c), mr);
}

extern "C" void kernel_launch(void* const* d_in, const int* in_sizes, int n_in,
                              void* d_out, int out_size) {
    const float* signal   = (const float*)d_in[0];
    const float* previous = (const float*)d_in[1];
    const float* hidden   = (const float*)d_in[2];
    const float* keys     = (const float*)d_in[3];
    const float* values   = (const float*)d_in[4];
    const float* strength = (const float*)d_in[5];
    const float* age      = (const float*)d_in[6];
    const float* wrq      = (const float*)d_in[7];
    const float* wrm      = (const float*)d_in[8];
    const float* brm      = (const float*)d_in[9];
    const float* wk       = (const float*)d_in[10];
    const float* bk       = (const float*)d_in[11];
    const float* wv       = (const float*)d_in[12];
    const float* bv       = (const float*)d_in[13];
    const float* ww       = (const float*)d_in[14];
    const float* bw       = (const float*)d_in[15];
    const float* wp       = (const float*)d_in[16];
    const float* bp       = (const float*)d_in[17];
    const float* wm       = (const float*)d_in[18];
    const float* bm       = (const float*)d_in[19];

    const int B = in_sizes[0] / DD;

    float* out = (float*)d_out;
    float* out_mr = out;
    float* out_k = out_mr + (size_t)B * DD;
    float* out_v = out_k + (size_t)B * NSLOT * DD;
    float* out_s = out_v + (size_t)B * NSLOT * DD;
    float* out_a = out_s + (size_t)B * NSLOT;

    const int SMEM_GEMM = 55296;
    static int s_attr_done = 0;
    if (!s_attr_done) {
        cudaFuncSetAttribute(gemm_mma, cudaFuncAttributeMaxDynamicSharedMemorySize, SMEM_GEMM);
        s_attr_done = 1;
    }

    prep_wt<<<dim3(128, 3), 256>>>(wrq, wk, wv);
    gemm_mma<<<dim3(B / 128, 2, 3), 256, SMEM_GEMM>>>(signal, previous, hidden, bk, bv, B);
    epilogue<<<(B + 7) / 8, 256>>>(signal, previous, hidden, keys, values, strength, age,
                                   wrm, brm, ww, bw, wp, bp, wm, bm,
                                   out_mr, out_k, out_v, out_s, out_a, B);
}

// round 12
// speedup vs baseline: 1.6257x; 1.0369x over previous
#include <cuda_runtime.h>
#include <cuda_bf16.h>
#include <math.h>

#define DD 128
#define KK 256
#define NSLOT 8
#define BMAX 32768

// scratch: [query_raw | candidate_key | candidate_value], each B x 128 fp32
__device__ float g_scratch[3ull * BMAX * DD];
// pre-transposed weights, bf16 hi/lo split: [mid][hi/lo][n*256+k]
__device__ __nv_bfloat16 g_wt[3][2][DD * KK];

// ---------------- helpers ----------------
__device__ __forceinline__ unsigned smem_u32(const void* p) {
    unsigned a;
    asm("{ .reg .u64 t; cvta.to.shared.u64 t, %1; cvt.u32.u64 %0, t; }" : "=r"(a) : "l"(p));
    return a;
}
__device__ __forceinline__ void ldmat4(unsigned* r, unsigned addr) {
    asm volatile("ldmatrix.sync.aligned.m8n8.x4.shared.b16 {%0,%1,%2,%3}, [%4];"
                 : "=r"(r[0]), "=r"(r[1]), "=r"(r[2]), "=r"(r[3])
                 : "r"(addr));
}
__device__ __forceinline__ void mma_bf16(float* d, const unsigned* a, unsigned b0, unsigned b1) {
    asm volatile(
        "mma.sync.aligned.m16n8k16.row.col.f32.bf16.bf16.f32 "
        "{%0,%1,%2,%3}, {%4,%5,%6,%7}, {%8,%9}, {%0,%1,%2,%3};"
        : "+f"(d[0]), "+f"(d[1]), "+f"(d[2]), "+f"(d[3])
        : "r"(a[0]), "r"(a[1]), "r"(a[2]), "r"(a[3]), "r"(b0), "r"(b1));
}
__device__ __forceinline__ void cp16(unsigned smem_addr, const void* gptr) {
    asm volatile("cp.async.ca.shared.global [%0], [%1], 16;"
                 :: "r"(smem_addr), "l"(gptr) : "memory");
}
__device__ __forceinline__ unsigned bf2u(__nv_bfloat162 v) {
    return *reinterpret_cast<unsigned*>(&v);
}
__device__ __forceinline__ float fast_tanh(float x) {
    float e = __expf(2.0f * x);
    return 1.0f - 2.0f / (e + 1.0f);
}
__device__ __forceinline__ float warp_sum(float v) {
#pragma unroll
    for (int o = 16; o; o >>= 1) v += __shfl_xor_sync(0xffffffffu, v, o);
    return v;
}
__device__ __forceinline__ float sigm(float x) { return 1.0f / (1.0f + expf(-x)); }
__device__ __forceinline__ float dot4(float4 a, float4 b) {
    return a.x * b.x + a.y * b.y + a.z * b.z + a.w * b.w;
}

// ---------------------------------------------------------------------------
// Kernel 0: transpose + bf16-split weights. W[k][n] -> Wt_hi/lo[n][k].
// ---------------------------------------------------------------------------
__global__ __launch_bounds__(256)
void prep_wt(const float* __restrict__ wrq, const float* __restrict__ wk,
             const float* __restrict__ wv) {
    const int mid = blockIdx.y;
    const float* W = (mid == 0) ? wrq : (mid == 1 ? wk : wv);
    int tid = blockIdx.x * 256 + threadIdx.x;  // 0..32767
    int k = tid >> 7;
    int n = tid & 127;
    float x = W[k * DD + n];
    __nv_bfloat16 hi = __float2bfloat16(x);
    float lo = x - __bfloat162float(hi);
    g_wt[mid][0][n * KK + k] = hi;
    g_wt[mid][1][n * KK + k] = __float2bfloat16(lo);
}

// ---------------------------------------------------------------------------
// Kernel 1: bf16-split GEMM via mma.sync. blockIdx.y = matrix id.
//   Block: 128 rows x 128 cols (FULL N) -> A filled/converted once per mid.
//   K=256 in 4 quarters of 64. fp32 accum; products Ah*Bh + Ah*Bl + Al*Bh.
//   B tiles fetched with cp.async, overlapped with in-register A conversion.
// Smem: A hi/lo [128][72] bf16 (144B pitch), B hi/lo [128][72] bf16. 72KB.
// ---------------------------------------------------------------------------
#define APITCH_B 144
__global__ __launch_bounds__(256, 2)
void gemm_mma(const float* __restrict__ signal,
              const float* __restrict__ previous,
              const float* __restrict__ hidden,
              const float* __restrict__ bk, const float* __restrict__ bv,
              int B) {
    extern __shared__ __align__(16) char smem[];
    const unsigned A_H = 0;
    const unsigned A_L = 128 * APITCH_B;       // 18432
    const unsigned B_H = 2u * 128 * APITCH_B;  // 36864
    const unsigned B_L = 3u * 128 * APITCH_B;  // 55296; total 73728
    const unsigned sb = smem_u32(smem);

    const int tid = threadIdx.x;
    const int wid = tid >> 5;
    const int lane = tid & 31;
    const int mid = blockIdx.y;
    const int row0 = blockIdx.x * 128;
    const float* X2 = (mid == 0) ? previous : hidden;
    const __nv_bfloat16* wth = &g_wt[mid][0][0];
    const __nv_bfloat16* wtl = &g_wt[mid][1][0];

    float acc[4][4][4];
#pragma unroll
    for (int i = 0; i < 4; i++)
#pragma unroll
        for (int j = 0; j < 4; j++)
#pragma unroll
            for (int e = 0; e < 4; e++) acc[i][j][e] = 0.0f;

    // warp tile: rows wm..wm+63 (4 m-atoms of 16), cols wn..wn+31 (4 n-atoms of 8)
    const int wm = (wid & 1) * 64;
    const int wn = (wid >> 1) * 32;
    // ldmatrix lane offsets (identical fragment mapping to validated round)
    const unsigned aOff = (unsigned)(wm + (lane & 15)) * APITCH_B + (lane >> 4) * 16;
    const unsigned bOff = (unsigned)(wn + ((lane >> 4) & 1) * 8 + (lane & 7)) * APITCH_B +
                          ((lane >> 3) & 1) * 16;

    for (int q = 0; q < 4; q++) {
        const int kbase = q * 64;
        const float* Xsrc = (kbase < DD) ? signal : X2;
        const int kloc = kbase & (DD - 1);

        // 1) B fill via cp.async: 128 n x 64 k hi + lo = 2048 x 16B chunks
#pragma unroll
        for (int i = 0; i < 4; i++) {
            int u = tid + i * 256;       // 0..1023
            int n = u >> 3, kc = u & 7;  // 8 chunks of 16B per n-row
            unsigned dst = (unsigned)n * APITCH_B + kc * 16;
            size_t src = (size_t)n * KK + kbase + kc * 8;
            cp16(sb + B_H + dst, wth + src);
            cp16(sb + B_L + dst, wtl + src);
        }
        asm volatile("cp.async.commit_group;" ::: "memory");

        // 2) A fill (overlaps the cp.async): 128 rows x 64 k fp32 -> bf16 split
#pragma unroll
        for (int i = 0; i < 8; i++) {
            int f = tid + i * 256;
            int r = f >> 4, c4 = f & 15;
            float4 x = *reinterpret_cast<const float4*>(
                Xsrc + (size_t)(row0 + r) * DD + kloc + c4 * 4);
            __nv_bfloat162 h0 = __float22bfloat162_rn(make_float2(x.x, x.y));
            __nv_bfloat162 h1 = __float22bfloat162_rn(make_float2(x.z, x.w));
            float2 hf0 = __bfloat1622float2(h0);
            float2 hf1 = __bfloat1622float2(h1);
            __nv_bfloat162 l0 = __float22bfloat162_rn(make_float2(x.x - hf0.x, x.y - hf0.y));
            __nv_bfloat162 l1 = __float22bfloat162_rn(make_float2(x.z - hf1.x, x.w - hf1.y));
            unsigned off = (unsigned)r * APITCH_B + c4 * 8;
            *reinterpret_cast<uint2*>(smem + A_H + off) = make_uint2(bf2u(h0), bf2u(h1));
            *reinterpret_cast<uint2*>(smem + A_L + off) = make_uint2(bf2u(l0), bf2u(l1));
        }
        asm volatile("cp.async.wait_group 0;" ::: "memory");
        __syncthreads();

#pragma unroll
        for (int ks = 0; ks < 4; ks++) {
            unsigned bh[8], bl[8];
            ldmat4(bh, sb + B_H + bOff + ks * 32);
            ldmat4(bh + 4, sb + B_H + bOff + 16u * APITCH_B + ks * 32);
            ldmat4(bl, sb + B_L + bOff + ks * 32);
            ldmat4(bl + 4, sb + B_L + bOff + 16u * APITCH_B + ks * 32);
#pragma unroll
            for (int am = 0; am < 4; am++) {
                unsigned ah[4], al[4];
                unsigned aoff = aOff + (unsigned)am * (16 * APITCH_B) + ks * 32;
                ldmat4(ah, sb + A_H + aoff);
                ldmat4(al, sb + A_L + aoff);
#pragma unroll
                for (int bn = 0; bn < 4; bn++) {
                    unsigned b0 = (bn & 1) ? ((bn & 2) ? bh[6] : bh[2]) : ((bn & 2) ? bh[4] : bh[0]);
                    unsigned b1 = (bn & 1) ? ((bn & 2) ? bh[7] : bh[3]) : ((bn & 2) ? bh[5] : bh[1]);
                    unsigned c0 = (bn & 1) ? ((bn & 2) ? bl[6] : bl[2]) : ((bn & 2) ? bl[4] : bl[0]);
                    unsigned c1 = (bn & 1) ? ((bn & 2) ? bl[7] : bl[3]) : ((bn & 2) ? bl[5] : bl[1]);
                    mma_bf16(acc[am][bn], ah, b0, b1);
                    mma_bf16(acc[am][bn], ah, c0, c1);
                    mma_bf16(acc[am][bn], al, b0, b1);
                }
            }
        }
        __syncthreads();
    }

    // writeback: d0,d1 -> row (lane>>2), cols (lane&3)*2..+1; d2,d3 -> row+8
    float* out = g_scratch + (size_t)mid * B * DD;
    const float* bias = (mid == 1) ? bk : bv;
    const int qrow = lane >> 2;
    const int qcol = (lane & 3) * 2;
#pragma unroll
    for (int am = 0; am < 4; am++) {
        int r0 = row0 + wm + am * 16 + qrow;
#pragma unroll
        for (int bn = 0; bn < 4; bn++) {
            int cc = wn + bn * 8 + qcol;
            float2 v0 = make_float2(acc[am][bn][0], acc[am][bn][1]);
            float2 v1 = make_float2(acc[am][bn][2], acc[am][bn][3]);
            if (mid != 0) {
                float2 bb = *reinterpret_cast<const float2*>(bias + cc);
                v0.x = fast_tanh(v0.x + bb.x);
                v0.y = fast_tanh(v0.y + bb.y);
                v1.x = fast_tanh(v1.x + bb.x);
                v1.y = fast_tanh(v1.y + bb.y);
            }
            *reinterpret_cast<float2*>(out + (size_t)r0 * DD + cc) = v0;
            *reinterpret_cast<float2*>(out + (size_t)(r0 + 8) * DD + cc) = v1;
        }
    }
}

// ---------------------------------------------------------------------------
// Kernel 2: per-row epilogue (unchanged; at LTS-cap roofline).
// ---------------------------------------------------------------------------
__global__ __launch_bounds__(256, 3)
void epilogue(const float* __restrict__ signal,
              const float* __restrict__ previous,
              const float* __restrict__ hidden,
              const float* __restrict__ keys,
              const float* __restrict__ values,
              const float* __restrict__ strength,
              const float* __restrict__ age,
              const float* __restrict__ wrm, const float* __restrict__ brm,
              const float* __restrict__ ww, const float* __restrict__ bw,
              const float* __restrict__ wp, const float* __restrict__ bp,
              const float* __restrict__ wm, const float* __restrict__ bm,
              float* __restrict__ out_mr,
              float* __restrict__ out_k,
              float* __restrict__ out_v,
              float* __restrict__ out_s,
              float* __restrict__ out_a,
              int B) {
    const int warp = threadIdx.x >> 5;
    const int lane = threadIdx.x & 31;
    const int row = blockIdx.x * 8 + warp;
    if (row >= B) return;
    const size_t rb = (size_t)row * DD;
    const int c = lane * 4;

    const float4 s4 = __ldcs(reinterpret_cast<const float4*>(signal + rb + c));
    const float4 p4 = __ldcs(reinterpret_cast<const float4*>(previous + rb + c));
    const float4 h4 = __ldcs(reinterpret_cast<const float4*>(hidden + rb + c));
    const float4 q4 = __ldcs(reinterpret_cast<const float4*>(g_scratch + rb + c));
    const float4 ck4 = __ldcs(reinterpret_cast<const float4*>(g_scratch + (size_t)B * DD + rb + c));

    float g0, g1, g2, g3, qn, ckn;
    {
        const float4 wrm0 = *reinterpret_cast<const float4*>(wrm + c);
        const float4 wrm1 = *reinterpret_cast<const float4*>(wrm + DD + c);
        const float4 ww0 = *reinterpret_cast<const float4*>(ww + c);
        const float4 ww1 = *reinterpret_cast<const float4*>(ww + DD + c);
        const float4 wp0 = *reinterpret_cast<const float4*>(wp + c);
        const float4 wp1 = *reinterpret_cast<const float4*>(wp + DD + c);
        const float4 wm0 = *reinterpret_cast<const float4*>(wm + c);
        const float4 wm1 = *reinterpret_cast<const float4*>(wm + DD + c);
        g0 = warp_sum(dot4(s4, wrm0) + dot4(p4, wrm1));
        g1 = warp_sum(dot4(s4, ww0) + dot4(h4, ww1));
        g2 = warp_sum(dot4(s4, wp0) + dot4(h4, wp1));
        g3 = warp_sum(dot4(s4, wm0) + dot4(h4, wm1));
        qn = warp_sum(dot4(q4, q4));
        ckn = warp_sum(dot4(ck4, ck4));
    }
    const float rm = sigm(g0 + brm[0]);
    const float wsg = sigm(g1 + bw[0]);
    const float pers = sigm(g2 + bp[0]);
    const float mlog = g3 + bm[0];
    const float qinv = 1.0f / fmaxf(sqrtf(qn), 1e-6f);
    const float ckinv = 1.0f / fmaxf(sqrtf(ckn), 1e-6f);

    const size_t kb = (size_t)row * NSLOT * DD;

    float knp[8], qdp[8], cdp[8];
#pragma unroll
    for (int n = 0; n < 8; n++) {
        float4 k4 = *reinterpret_cast<const float4*>(keys + kb + n * DD + c);
        knp[n] = dot4(k4, k4);
        qdp[n] = dot4(q4, k4);
        cdp[n] = dot4(ck4, k4);
    }
    float cs[8], sim[8];
#pragma unroll
    for (int n = 0; n < 8; n++) {
        float kn = warp_sum(knp[n]);
        float qd = warp_sum(qdp[n]);
        float cd = warp_sum(cdp[n]);
        float kinv = 1.0f / fmaxf(sqrtf(kn), 1e-6f);
        cs[n] = qd * qinv * kinv;
        sim[n] = cd * ckinv * kinv;
    }

    const float myst = (lane < 8) ? strength[(size_t)row * 8 + lane] : 0.0f;
    const float myag = (lane < 8) ? age[(size_t)row * 8 + lane] : 0.0f;
    const float ps_self = (2.4f * myst + 0.6f * (1.0f - myag)) * 4.0f;
    const float rp_self = 1.2f * myag + (1.0f - myst);

    float w[8];
    {
        float cmax = -1e30f, pmax = -1e30f;
        float ps[8];
#pragma unroll
        for (int n = 0; n < 8; n++) {
            cmax = fmaxf(cmax, cs[n]);
            ps[n] = __shfl_sync(0xffffffffu, ps_self, n);
            pmax = fmaxf(pmax, ps[n]);
        }
        float csum = 0.0f, psum = 0.0f;
        float cw[8];
#pragma unroll
        for (int n = 0; n < 8; n++) {
            cw[n] = expf((cs[n] - cmax) * 4.0f);
            csum += cw[n];
            ps[n] = expf(ps[n] - pmax);
            psum += ps[n];
        }
        float ci = rm / csum, pi = (1.0f - rm) / psum;
#pragma unroll
        for (int n = 0; n < 8; n++) w[n] = cw[n] * ci + ps[n] * pi;
    }

    float s0 = -1e30f; int i0 = 0;
#pragma unroll
    for (int n = 0; n < 8; n++) if (sim[n] > s0) { s0 = sim[n]; i0 = n; }
    float s1 = -1e30f; int i1 = 0;
#pragma unroll
    for (int n = 0; n < 8; n++) if (n != i0 && sim[n] > s1) { s1 = sim[n]; i1 = n; }
    float s2 = -1e30f; int i2 = 0;
#pragma unroll
    for (int n = 0; n < 8; n++) if (n != i0 && n != i1 && sim[n] > s2) { s2 = sim[n]; i2 = n; }

    const float nov = fminf(fmaxf(1.0f - s0, 0.0f), 1.0f);

    float rbest = -1e30f; int ri = 0;
#pragma unroll
    for (int n = 0; n < 8; n++) {
        float rs = __shfl_sync(0xffffffffu, rp_self, n) + 0.5f * (1.0f - sim[n]);
        if (rs > rbest) { rbest = rs; ri = n; }
    }

    const float mpref = sigm(mlog + 2.6f * s0);
    const bool full_m = (s0 > 0.78f) && (mpref >= 0.55f);
    const bool multi_m = full_m && (s1 > 0.68f);
    const bool partial_m = (!multi_m) && (s0 > 0.64f) && (s1 > 0.52f);
    const bool merge_like = full_m || partial_m || multi_m;

    const float pe = expf((s1 - s0) * 4.0f);
    const float pw0 = 1.0f / (1.0f + pe), pw1 = pe / (1.0f + pe);
    const float me1 = pe, me2 = expf((s2 - s0) * 4.0f);
    const float minv = 1.0f / (1.0f + me1 + me2);
    const float mw0 = minv, mw1 = me1 * minv, mw2 = me2 * minv;

    const float scale = multi_m ? (0.16f + 0.52f * wsg)
                                : (partial_m ? (0.18f + 0.62f * wsg) : (0.2f + 0.8f * wsg));
    const float osc = scale * (0.55f + 0.45f * nov);
    const float kmix = (merge_like ? (0.28f + 0.24f * pers) : (0.78f + 0.16f * pers)) * osc;
    const float vmix = (merge_like ? (0.42f + 0.28f * pers) : (0.82f + 0.12f * pers)) * osc;
    const float bf = 0.45f + 0.35f * pers + 0.45f * nov + 0.25f * wsg;

    float ow[8];
#pragma unroll
    for (int n = 0; n < 8; n++) {
        float tw = (n == ri) ? 1.0f : 0.0f;
        if (full_m) tw = (n == i0) ? 1.0f : 0.0f;
        if (partial_m) tw = (n == i0) ? pw0 : ((n == i1) ? pw1 : 0.0f);
        if (multi_m) tw = (n == i0) ? mw0 : ((n == i1) ? mw1 : ((n == i2) ? mw2 : 0.0f));
        ow[n] = tw;
    }

    const float4 cv4 = __ldcs(reinterpret_cast<const float4*>(g_scratch + 2ull * (size_t)B * DD + rb + c));

    float4 mr = make_float4(0, 0, 0, 0);
#pragma unroll
    for (int n = 0; n < 8; n++) {
        float4 k4 = *reinterpret_cast<const float4*>(keys + kb + n * DD + c);
        float4 v4 = *reinterpret_cast<const float4*>(values + kb + n * DD + c);
        float wn = w[n];
        mr.x = fmaf(wn, v4.x, mr.x);
        mr.y = fmaf(wn, v4.y, mr.y);
        mr.z = fmaf(wn, v4.z, mr.z);
        mr.w = fmaf(wn, v4.w, mr.w);

        float fk = ow[n] * kmix;
        float4 uk;
        uk.x = k4.x + fk * (ck4.x - k4.x);
        uk.y = k4.y + fk * (ck4.y - k4.y);
        uk.z = k4.z + fk * (ck4.z - k4.z);
        uk.w = k4.w + fk * (ck4.w - k4.w);
        __stcs(reinterpret_cast<float4*>(out_k + kb + n * DD + c), uk);

        float fv = ow[n] * vmix;
        float4 uv;
        uv.x = v4.x + fv * (cv4.x - v4.x);
        uv.y = v4.y + fv * (cv4.y - v4.y);
        uv.z = v4.z + fv * (cv4.z - v4.z);
        uv.w = v4.w + fv * (cv4.w - v4.w);
        __stcs(reinterpret_cast<float4*>(out_v + kb + n * DD + c), uv);

        if (lane == n) {
            float o = ow[n] * osc;
            out_s[(size_t)row * 8 + n] = fminf(fmaxf(myst * 0.99f + o * bf, 0.0f), 1.0f);
            out_a[(size_t)row * 8 + n] = fminf(fmaxf((myag + 0.02f) * (1.0f - o), 0.0f), 1.0f);
        }
    }
    __stcs(reinterpret_cast<float4*>(out_mr + rb + c), mr);
}

extern "C" void kernel_launch(void* const* d_in, const int* in_sizes, int n_in,
                              void* d_out, int out_size) {
    const float* signal   = (const float*)d_in[0];
    const float* previous = (const float*)d_in[1];
    const float* hidden   = (const float*)d_in[2];
    const float* keys     = (const float*)d_in[3];
    const float* values   = (const float*)d_in[4];
    const float* strength = (const float*)d_in[5];
    const float* age      = (const float*)d_in[6];
    const float* wrq      = (const float*)d_in[7];
    const float* wrm      = (const float*)d_in[8];
    const float* brm      = (const float*)d_in[9];
    const float* wk       = (const float*)d_in[10];
    const float* bk       = (const float*)d_in[11];
    const float* wv       = (const float*)d_in[12];
    const float* bv       = (const float*)d_in[13];
    const float* ww       = (const float*)d_in[14];
    const float* bw       = (const float*)d_in[15];
    const float* wp       = (const float*)d_in[16];
    const float* bp       = (const float*)d_in[17];
    const float* wm       = (const float*)d_in[18];
    const float* bm       = (const float*)d_in[19];

    const int B = in_sizes[0] / DD;

    float* out = (float*)d_out;
    float* out_mr = out;
    float* out_k = out_mr + (size_t)B * DD;
    float* out_v = out_k + (size_t)B * NSLOT * DD;
    float* out_s = out_v + (size_t)B * NSLOT * DD;
    float* out_a = out_s + (size_t)B * NSLOT;

    const int SMEM_GEMM = 73728;
    static int s_attr_done = 0;
    if (!s_attr_done) {
        cudaFuncSetAttribute(gemm_mma, cudaFuncAttributeMaxDynamicSharedMemorySize, SMEM_GEMM);
        s_attr_done = 1;
    }

    prep_wt<<<dim3(128, 3), 256>>>(wrq, wk, wv);
    gemm_mma<<<dim3(B / 128, 3), 256, SMEM_GEMM>>>(signal, previous, hidden, bk, bv, B);
    epilogue<<<(B + 7) / 8, 256>>>(signal, previous, hidden, keys, values, strength, age,
                                   wrm, brm, ww, bw, wp, bp, wm, bm,
                                   out_mr, out_k, out_v, out_s, out_a, B);
}